// round 1
// baseline (speedup 1.0000x reference)
#include <cuda_runtime.h>
#include <cstdint>
#include <cstddef>

#define BM       128
#define THREADS  512
#define SMEM_BYTES ((BM*260 + 256*68) * 4)   // 202752 bytes

// ---------------- device-global scratch (no allocations allowed) ----------------
__device__ float g_w1[256*256];    // wn(v1,g1), tf32-rounded
__device__ float g_w2[256*256];    // wn(v2,g2), tf32-rounded
__device__ float g_w3[512*256];    // wn(v3,g3), tf32-rounded
__device__ float g_wc[512*256];    // wn(v_cond,g_cond), full fp32
__device__ float g_gamma[256*256]; // per-group FiLM gamma (incl. +1)
__device__ float g_beta [256*256]; // per-group FiLM beta

__device__ __forceinline__ float tf32r(float x){
  uint32_t u; asm("cvt.rna.tf32.f32 %0, %1;" : "=r"(u) : "f"(x));
  return __uint_as_float(u);
}

__device__ __forceinline__ void mma8(float* c,
    uint32_t a0,uint32_t a1,uint32_t a2,uint32_t a3,uint32_t b0,uint32_t b1){
  asm volatile("mma.sync.aligned.m16n8k8.row.col.f32.tf32.tf32.f32 "
    "{%0,%1,%2,%3}, {%4,%5,%6,%7}, {%8,%9}, {%0,%1,%2,%3};"
    : "+f"(c[0]), "+f"(c[1]), "+f"(c[2]), "+f"(c[3])
    : "r"(a0),"r"(a1),"r"(a2),"r"(a3),"r"(b0),"r"(b1));
}

// ---------------- precompute: weight-norm rows ----------------
// which: 0->g_w1(256 rows), 1->g_w2(256), 2->g_w3(512), 3->g_wc(512, no tf32 round)
__global__ void wn_kernel(const float* __restrict__ v, const float* __restrict__ gsc, int which){
  float* w; int rnd = 1;
  if      (which==0) w = g_w1;
  else if (which==1) w = g_w2;
  else if (which==2) w = g_w3;
  else { w = g_wc; rnd = 0; }
  int row = blockIdx.x, tid = threadIdx.x, lane = tid & 31;
  float val = v[(size_t)row*256 + tid];
  float sq = val*val;
  #pragma unroll
  for (int o=16;o;o>>=1) sq += __shfl_xor_sync(0xffffffffu, sq, o);
  __shared__ float red[8];
  __shared__ float s_scale;
  if (lane==0) red[tid>>5] = sq;
  __syncthreads();
  if (tid==0){
    float tot=0.f;
    #pragma unroll
    for (int i=0;i<8;i++) tot += red[i];
    s_scale = gsc[row]*rsqrtf(tot);
  }
  __syncthreads();
  float o = val * s_scale;
  if (rnd) o = tf32r(o);
  w[(size_t)row*256 + tid] = o;
}

// ---------------- precompute: FiLM gamma/beta per group ----------------
// gb[g][j] = cond[g] . g_wc[j] + b_cond[j]; gamma=gb[:, :256]+1; beta=gb[:,256:]
// block = 256 threads, handles 4 groups; each warp covers j = wid + 8*jj.
__global__ void film_kernel(const float* __restrict__ cond, const float* __restrict__ b_cond){
  __shared__ float cs[4][256];
  int tid=threadIdx.x, lane=tid&31, wid=tid>>5;
  int g0 = blockIdx.x*4;
  for (int i=tid; i<1024; i+=256)
    cs[i>>8][i&255] = cond[(size_t)(g0+(i>>8))*256 + (i&255)];
  __syncthreads();
  for (int jj=0; jj<64; jj++){
    int j = wid + jj*8;
    float w8[8];
    #pragma unroll
    for (int q=0;q<8;q++) w8[q] = g_wc[(size_t)j*256 + lane + 32*q];
    float bc = b_cond[j];
    #pragma unroll
    for (int gi=0; gi<4; gi++){
      float s=0.f;
      #pragma unroll
      for (int q=0;q<8;q++) s = fmaf(w8[q], cs[gi][lane+32*q], s);
      #pragma unroll
      for (int o=16;o;o>>=1) s += __shfl_xor_sync(0xffffffffu, s, o);
      if (lane==0){
        float val = s + bc;
        if (j < 256) g_gamma[(size_t)(g0+gi)*256 + j]        = val + 1.f;
        else         g_beta [(size_t)(g0+gi)*256 + (j-256)]  = val;
      }
    }
  }
}

// ---------------- fused mainloop ----------------
// Per-warp output tile 32x64 (mt=2 x 16 rows, nt=8 x 8 cols); 16 warps cover 128x256.
// A = smem activation tile [BM][260] (pad 260 -> conflict-free frag loads).
// Wg streamed in k-chunks of 64 into wbuf[256][68].
__device__ __forceinline__ void gemm_tile(
    const float* __restrict__ A,
    float* __restrict__ wbuf,
    const float* __restrict__ Wg,
    int n_base, int wm, int wn, int g, int t, int tid,
    float acc[2][8][4])
{
  #pragma unroll
  for (int i=0;i<2;i++)
    #pragma unroll
    for (int j=0;j<8;j++)
      #pragma unroll
      for (int q=0;q<4;q++) acc[i][j][q]=0.f;

  for (int kc = 0; kc < 4; kc++) {
    // stage weight chunk: 256 rows x 64 k (fp32) -> wbuf, coalesced float4
    #pragma unroll
    for (int it = 0; it < 8; it++) {
      int idx = tid + it*THREADS;        // 4096 float4
      int row = idx >> 4;
      int c4  = idx & 15;
      float4 v = *(const float4*)(Wg + (size_t)(n_base+row)*256 + kc*64 + c4*4);
      *(float4*)(wbuf + row*68 + c4*4) = v;
    }
    __syncthreads();
    #pragma unroll
    for (int k8 = 0; k8 < 8; k8++) {
      int kk = kc*64 + k8*8;
      uint32_t a[2][4];
      #pragma unroll
      for (int mt=0; mt<2; mt++){
        const float* ab = A + (wm*32 + mt*16 + g)*260 + kk;
        a[mt][0] = __float_as_uint(ab[t]);
        a[mt][1] = __float_as_uint(ab[8*260 + t]);
        a[mt][2] = __float_as_uint(ab[t+4]);
        a[mt][3] = __float_as_uint(ab[8*260 + t + 4]);
      }
      #pragma unroll
      for (int nt=0; nt<8; nt++){
        const float* bb = wbuf + (wn*64 + nt*8 + g)*68 + k8*8;
        uint32_t b0 = __float_as_uint(bb[t]);
        uint32_t b1 = __float_as_uint(bb[t+4]);
        mma8(acc[0][nt], a[0][0],a[0][1],a[0][2],a[0][3], b0, b1);
        mma8(acc[1][nt], a[1][0],a[1][1],a[1][2],a[1][3], b0, b1);
      }
    }
    __syncthreads();
  }
}

__global__ void __launch_bounds__(THREADS,1) fused_kernel(
  const float* __restrict__ x, const int* __restrict__ bids,
  const float* __restrict__ b2, const float* __restrict__ b3,
  float* __restrict__ out, int N)
{
  extern __shared__ float sm[];
  float* as   = sm;             // [BM][260]
  float* wbuf = sm + BM*260;    // [256][68]
  int tid = threadIdx.x, lane = tid&31, wid = tid>>5;
  int wm = wid>>2, wn = wid&3;
  int g = lane>>2, t = lane&3;
  int rowBase = blockIdx.x*BM;

  // load x tile (tf32-round)
  #pragma unroll
  for (int it=0; it<16; it++){
    int idx = tid + it*THREADS;    // 8192 float4
    int r = idx>>6, c4 = idx&63;
    int gr = rowBase + r; if (gr >= N) gr = N-1;
    float4 v = *(const float4*)(x + (size_t)gr*256 + c4*4);
    v.x=tf32r(v.x); v.y=tf32r(v.y); v.z=tf32r(v.z); v.w=tf32r(v.w);
    *(float4*)(as + r*260 + c4*4) = v;
  }
  __syncthreads();

  float acc[2][8][4];

  // ---- GEMM1: h = x @ W1^T ----
  gemm_tile(as, wbuf, g_w1, 0, wm, wn, g, t, tid, acc);
  #pragma unroll
  for (int mt=0; mt<2; mt++)
    #pragma unroll
    for (int nt=0; nt<8; nt++){
      int r = wm*32+mt*16+g, c = wn*64+nt*8+2*t;
      as[r*260+c]       = acc[mt][nt][0];
      as[r*260+c+1]     = acc[mt][nt][1];
      as[(r+8)*260+c]   = acc[mt][nt][2];
      as[(r+8)*260+c+1] = acc[mt][nt][3];
    }
  __syncthreads();

  // ---- layernorm + FiLM + relu (warp handles 8 rows) ----
  #pragma unroll 1
  for (int rr=0; rr<8; rr++){
    int r = wid*8 + rr;
    float v[8]; float s=0.f, ss=0.f;
    #pragma unroll
    for (int q=0;q<8;q++){ float z = as[r*260 + lane + 32*q]; v[q]=z; s+=z; ss+=z*z; }
    #pragma unroll
    for (int o=16;o;o>>=1){ s+=__shfl_xor_sync(0xffffffffu,s,o); ss+=__shfl_xor_sync(0xffffffffu,ss,o); }
    float mu  = s*(1.f/256.f);
    float var = fmaf(-mu, mu, ss*(1.f/256.f));
    float rs  = rsqrtf(var + 1e-5f);
    int gr = rowBase + r; if (gr >= N) gr = N-1;
    int bi = bids[gr];
    const float* ga = g_gamma + (size_t)bi*256;
    const float* be = g_beta  + (size_t)bi*256;
    #pragma unroll
    for (int q=0;q<8;q++){
      int c = lane + 32*q;
      float val = fmaf((v[q]-mu)*rs, ga[c], be[c]);
      as[r*260+c] = tf32r(fmaxf(val, 0.f));
    }
  }
  __syncthreads();

  // ---- GEMM2: h = relu(h @ W2^T + b2) ----
  gemm_tile(as, wbuf, g_w2, 0, wm, wn, g, t, tid, acc);
  #pragma unroll
  for (int mt=0; mt<2; mt++)
    #pragma unroll
    for (int nt=0; nt<8; nt++){
      int r = wm*32+mt*16+g, c = wn*64+nt*8+2*t;
      float p = b2[c], q2 = b2[c+1];
      as[r*260+c]       = tf32r(fmaxf(acc[mt][nt][0]+p , 0.f));
      as[r*260+c+1]     = tf32r(fmaxf(acc[mt][nt][1]+q2, 0.f));
      as[(r+8)*260+c]   = tf32r(fmaxf(acc[mt][nt][2]+p , 0.f));
      as[(r+8)*260+c+1] = tf32r(fmaxf(acc[mt][nt][3]+q2, 0.f));
    }
  __syncthreads();

  // ---- GEMM3: logits = h @ W3^T + b3 (two 256-col halves) ----
  for (int nh=0; nh<2; nh++){
    gemm_tile(as, wbuf, g_w3, nh*256, wm, wn, g, t, tid, acc);
    #pragma unroll
    for (int mt=0; mt<2; mt++)
      #pragma unroll
      for (int nt=0; nt<8; nt++){
        int r = rowBase + wm*32+mt*16+g;
        int c = nh*256 + wn*64+nt*8+2*t;
        float p = b3[c], q2 = b3[c+1];
        if (r < N){
          float2 o0 = make_float2(acc[mt][nt][0]+p, acc[mt][nt][1]+q2);
          *(float2*)(out + (size_t)r*512 + c) = o0;
        }
        if (r+8 < N){
          float2 o1 = make_float2(acc[mt][nt][2]+p, acc[mt][nt][3]+q2);
          *(float2*)(out + (size_t)(r+8)*512 + c) = o1;
        }
      }
  }
}

// ---------------- launch ----------------
extern "C" void kernel_launch(void* const* d_in, const int* in_sizes, int n_in,
                              void* d_out, int out_size){
  const float* x      = (const float*)d_in[0];
  const float* cond   = (const float*)d_in[1];
  const int*   bids   = (const int*)  d_in[2];
  const float* v_cond = (const float*)d_in[3];
  const float* g_cond = (const float*)d_in[4];
  const float* b_cond = (const float*)d_in[5];
  const float* v1     = (const float*)d_in[6];
  const float* g1     = (const float*)d_in[7];
  const float* v2     = (const float*)d_in[8];
  const float* g2     = (const float*)d_in[9];
  const float* b2     = (const float*)d_in[10];
  const float* v3     = (const float*)d_in[11];
  const float* g3     = (const float*)d_in[12];
  const float* b3     = (const float*)d_in[13];
  float* out = (float*)d_out;
  int N = in_sizes[0] / 256;

  wn_kernel<<<256,256>>>(v1, g1, 0);
  wn_kernel<<<256,256>>>(v2, g2, 1);
  wn_kernel<<<512,256>>>(v3, g3, 2);
  wn_kernel<<<512,256>>>(v_cond, g_cond, 3);
  film_kernel<<<64,256>>>(cond, b_cond);

  cudaFuncSetAttribute(fused_kernel, cudaFuncAttributeMaxDynamicSharedMemorySize, SMEM_BYTES);
  int blocks = (N + BM - 1) / BM;
  fused_kernel<<<blocks, THREADS, SMEM_BYTES>>>(x, bids, b2, b3, out, N);
}

// round 3
// speedup vs baseline: 1.6561x; 1.6561x over previous
#include <cuda_runtime.h>
#include <cuda_fp16.h>
#include <cstdint>
#include <cstddef>

#define THREADS 512
// ---- dynamic smem layout (bytes from base) ----
#define OFF_A    0            // A tile fp16 [128][264]  -> 128*528 = 67584
#define A_STR    528          // bytes per row (264 halves)
#define OFF_RED  67584        // 1024 floats (sum[128][4], sumsq[128][4]) = 4096
#define OFF_W0   71680        // weight buf0 fp16 [256][136] = 69632
#define OFF_W1   141312       // weight buf1
#define WB_STR   272          // bytes per row (136 halves)
#define SMEM_NEED 210944

// ---- precomputed weights (device globals; no allocs allowed) ----
__device__ __half g_w1h[256*256];
__device__ __half g_w2h[256*256];
__device__ __half g_w3h[512*256];
__device__ float  g_wc[512*256];
__device__ float  g_gamma[256*256];
__device__ float  g_beta [256*256];

// ---------------- low-level helpers ----------------
__device__ __forceinline__ uint32_t smem_u32(const void* p){
  uint32_t a; asm("{ .reg .u64 t; cvta.to.shared.u64 t, %1; cvt.u32.u64 %0, t; }" : "=r"(a) : "l"(p));
  return a;
}
__device__ __forceinline__ uint32_t lds32(uint32_t a){
  uint32_t v; asm volatile("ld.shared.b32 %0, [%1];" : "=r"(v) : "r"(a)); return v;
}
__device__ __forceinline__ float ldsf(uint32_t a){
  float v; asm volatile("ld.shared.f32 %0, [%1];" : "=f"(v) : "r"(a)); return v;
}
__device__ __forceinline__ void sts32(uint32_t a, uint32_t v){
  asm volatile("st.shared.b32 [%0], %1;" :: "r"(a), "r"(v));
}
__device__ __forceinline__ void stsf(uint32_t a, float v){
  asm volatile("st.shared.f32 [%0], %1;" :: "r"(a), "f"(v));
}
__device__ __forceinline__ void sts64(uint32_t a, uint32_t v0, uint32_t v1){
  asm volatile("st.shared.v2.b32 [%0], {%1,%2};" :: "r"(a), "r"(v0), "r"(v1));
}
__device__ __forceinline__ void cpasync16(uint32_t dst, const void* src){
  asm volatile("{ .reg .u64 gp; cvta.to.global.u64 gp, %1; cp.async.cg.shared.global [%0], [gp], 16; }"
               :: "r"(dst), "l"(src));
}
#define CPCOMMIT() asm volatile("cp.async.commit_group;" ::: "memory")
#define CPWAIT1()  asm volatile("cp.async.wait_group 1;" ::: "memory")
#define CPWAIT0()  asm volatile("cp.async.wait_group 0;" ::: "memory")

__device__ __forceinline__ void mma16816(float* c,
    uint32_t a0,uint32_t a1,uint32_t a2,uint32_t a3,uint32_t b0,uint32_t b1){
  asm volatile("mma.sync.aligned.m16n8k16.row.col.f32.f16.f16.f32 "
    "{%0,%1,%2,%3}, {%4,%5,%6,%7}, {%8,%9}, {%0,%1,%2,%3};"
    : "+f"(c[0]), "+f"(c[1]), "+f"(c[2]), "+f"(c[3])
    : "r"(a0),"r"(a1),"r"(a2),"r"(a3),"r"(b0),"r"(b1));
}
__device__ __forceinline__ uint32_t pack_h2(float x, float y){
  __half2 h = __floats2half2_rn(x, y);
  return *reinterpret_cast<uint32_t*>(&h);
}

// ---------------- precompute: weight-norm (one launch) ----------------
__global__ void wn_all(const float* __restrict__ v1, const float* __restrict__ g1,
                       const float* __restrict__ v2, const float* __restrict__ g2,
                       const float* __restrict__ v3, const float* __restrict__ g3,
                       const float* __restrict__ vc, const float* __restrict__ gc){
  int b = blockIdx.x, tid = threadIdx.x, lane = tid & 31;
  const float* v; const float* gs; __half* wh = nullptr; float* wf = nullptr; int row;
  if      (b < 256)  { v=v1; gs=g1; wh=g_w1h; row=b; }
  else if (b < 512)  { v=v2; gs=g2; wh=g_w2h; row=b-256; }
  else if (b < 1024) { v=v3; gs=g3; wh=g_w3h; row=b-512; }
  else               { v=vc; gs=gc; wf=g_wc;  row=b-1024; }
  float val = v[(size_t)row*256 + tid];
  float sq = val*val;
  #pragma unroll
  for (int o=16;o;o>>=1) sq += __shfl_xor_sync(0xffffffffu, sq, o);
  __shared__ float red[8]; __shared__ float s_scale;
  if (lane==0) red[tid>>5] = sq;
  __syncthreads();
  if (tid==0){
    float tot=0.f;
    #pragma unroll
    for (int i=0;i<8;i++) tot += red[i];
    s_scale = gs[row]*rsqrtf(tot);
  }
  __syncthreads();
  float o = val * s_scale;
  if (wh) wh[(size_t)row*256 + tid] = __float2half_rn(o);
  else    wf[(size_t)row*256 + tid] = o;
}

// ---------------- precompute: FiLM gamma/beta ----------------
__global__ void film_kernel(const float* __restrict__ cond, const float* __restrict__ b_cond){
  __shared__ float cs[4][256];
  int tid=threadIdx.x, lane=tid&31, wid=tid>>5;
  int g0 = blockIdx.x*4;
  for (int i=tid; i<1024; i+=256)
    cs[i>>8][i&255] = cond[(size_t)(g0+(i>>8))*256 + (i&255)];
  __syncthreads();
  for (int jj=0; jj<64; jj++){
    int j = wid + jj*8;
    float w8[8];
    #pragma unroll
    for (int q=0;q<8;q++) w8[q] = g_wc[(size_t)j*256 + lane + 32*q];
    float bc = b_cond[j];
    #pragma unroll
    for (int gi=0; gi<4; gi++){
      float s=0.f;
      #pragma unroll
      for (int q=0;q<8;q++) s = fmaf(w8[q], cs[gi][lane+32*q], s);
      #pragma unroll
      for (int o=16;o;o>>=1) s += __shfl_xor_sync(0xffffffffu, s, o);
      if (lane==0){
        float val = s + bc;
        if (j < 256) g_gamma[(size_t)(g0+gi)*256 + j]       = val + 1.f;
        else         g_beta [(size_t)(g0+gi)*256 + (j-256)] = val;
      }
    }
  }
}

// ---------------- main kernel pieces ----------------
// stage a [256 n x 128 k] fp16 chunk (64KB) into wbuf via cp.async
__device__ __forceinline__ void stage_async(const __half* __restrict__ base, uint32_t wbu, int tid){
  #pragma unroll
  for (int i=0;i<8;i++){
    int idx = tid + i*THREADS;          // 4096 x 16B
    int row = idx >> 4, c = idx & 15;   // c: 8-half (16B) unit
    cpasync16(wbu + (uint32_t)row*WB_STR + (uint32_t)c*16,
              base + (size_t)row*256 + c*8);
  }
}

// one K=128 chunk of mma for all 16 warps; aBase/bBase are per-thread smem addrs
__device__ __forceinline__ void mma_chunk(uint32_t aBase, uint32_t bBase, int kB,
                                          float acc[2][8][4]){
  uint32_t aP = aBase + (uint32_t)kB;
  uint32_t bP = bBase;
  #pragma unroll 1
  for (int k16=0; k16<8; k16++){
    uint32_t a[2][4];
    #pragma unroll
    for (int mt=0; mt<2; mt++){
      uint32_t ar = aP + (uint32_t)mt*(16*A_STR);
      a[mt][0]=lds32(ar);            a[mt][1]=lds32(ar + 8*A_STR);
      a[mt][2]=lds32(ar + 16);       a[mt][3]=lds32(ar + 8*A_STR + 16);
    }
    #pragma unroll
    for (int nt=0; nt<8; nt++){
      uint32_t br = bP + (uint32_t)nt*(8*WB_STR);
      uint32_t b0 = lds32(br), b1 = lds32(br + 16);
      mma16816(acc[0][nt], a[0][0],a[0][1],a[0][2],a[0][3], b0, b1);
      mma16816(acc[1][nt], a[1][0],a[1][1],a[1][2],a[1][3], b0, b1);
    }
    aP += 32; bP += 32;
  }
}

__device__ __forceinline__ void zacc(float acc[2][8][4]){
  #pragma unroll
  for (int i=0;i<2;i++)
    #pragma unroll
    for (int j=0;j<8;j++)
      #pragma unroll
      for (int q=0;q<4;q++) acc[i][j][q]=0.f;
}

// wait for current buffer, compute, then (optionally) prefetch chunk i+2 into this buffer
__device__ __forceinline__ void do_chunk(uint32_t aBase, uint32_t bBase, int kB, int last,
                                         float acc[2][8][4],
                                         const __half* nextW, uint32_t nextBuf, int tid){
  if (last) CPWAIT0(); else CPWAIT1();
  __syncthreads();
  mma_chunk(aBase, bBase, kB, acc);
  __syncthreads();
  if (nextW){ stage_async(nextW, nextBuf, tid); CPCOMMIT(); }
}

__global__ void __launch_bounds__(THREADS,1)
fused_kernel(const float* __restrict__ x, const int* __restrict__ bids,
             const float* __restrict__ b2, const float* __restrict__ b3,
             float* __restrict__ out, int N)
{
  extern __shared__ char smraw[];
  const uint32_t sb = smem_u32(smraw);

  const int tid = threadIdx.x, lane = tid & 31, wid = tid >> 5;
  const int wm = wid >> 2, wn = wid & 3;
  const int g = lane >> 2, t = lane & 3;
  const int rowBase = blockIdx.x * 128;

  // initial prefetch of W1's two K-chunks
  stage_async(g_w1h,        sb + OFF_W0, tid); CPCOMMIT();
  stage_async(g_w1h + 128,  sb + OFF_W1, tid); CPCOMMIT();

  // ---- load x tile -> A smem as fp16 ----
  #pragma unroll
  for (int i=0;i<16;i++){
    int idx = tid + i*THREADS;          // 8192 float4
    int r = idx >> 6, c4 = idx & 63;    // c4: 4-float unit
    int gr = rowBase + r; int grc = gr < N ? gr : N-1;
    float4 v = *(const float4*)(x + (size_t)grc*256 + c4*4);
    sts64(sb + OFF_A + (uint32_t)r*A_STR + (uint32_t)c4*8,
          pack_h2(v.x, v.y), pack_h2(v.z, v.w));
  }

  const uint32_t aBase = sb + OFF_A  + (uint32_t)(wm*32 + g)*A_STR + t*4;
  const uint32_t bB0   = sb + OFF_W0 + (uint32_t)(wn*64 + g)*WB_STR + t*4;
  const uint32_t bB1   = sb + OFF_W1 + (uint32_t)(wn*64 + g)*WB_STR + t*4;
  const uint32_t redS  = sb + OFF_RED;

  float acc[2][8][4];

  // ================= GEMM1 =================
  zacc(acc);
  do_chunk(aBase, bB0, 0,   0, acc, g_w2h,       sb + OFF_W0, tid);
  do_chunk(aBase, bB1, 256, 0, acc, g_w2h + 128, sb + OFF_W1, tid);

  // ---- epilogue 1: layernorm + FiLM + relu -> A ----
  {
    #pragma unroll
    for (int mt=0; mt<2; mt++){
      #pragma unroll
      for (int h=0; h<2; h++){
        float S=0.f, Q=0.f;
        #pragma unroll
        for (int nt=0; nt<8; nt++){
          float u = acc[mt][nt][2*h], v = acc[mt][nt][2*h+1];
          S += u + v; Q = fmaf(u,u,Q); Q = fmaf(v,v,Q);
        }
        S += __shfl_xor_sync(0xffffffffu, S, 1); S += __shfl_xor_sync(0xffffffffu, S, 2);
        Q += __shfl_xor_sync(0xffffffffu, Q, 1); Q += __shfl_xor_sync(0xffffffffu, Q, 2);
        int r = wm*32 + mt*16 + h*8 + g;
        if (t==0){
          stsf(redS + (uint32_t)(r*4 + wn)*4,        S);
          stsf(redS + (uint32_t)(512 + r*4 + wn)*4,  Q);
        }
      }
    }
    __syncthreads();
    #pragma unroll
    for (int mt=0; mt<2; mt++){
      #pragma unroll
      for (int h=0; h<2; h++){
        int r = wm*32 + mt*16 + h*8 + g;
        float S = ldsf(redS + (uint32_t)(r*4)*4)     + ldsf(redS + (uint32_t)(r*4+1)*4)
                + ldsf(redS + (uint32_t)(r*4+2)*4)   + ldsf(redS + (uint32_t)(r*4+3)*4);
        float Q = ldsf(redS + (uint32_t)(512+r*4)*4) + ldsf(redS + (uint32_t)(512+r*4+1)*4)
                + ldsf(redS + (uint32_t)(512+r*4+2)*4)+ ldsf(redS + (uint32_t)(512+r*4+3)*4);
        float mu = S*(1.f/256.f);
        float var = fmaf(-mu, mu, Q*(1.f/256.f));
        float rs = rsqrtf(var + 1e-5f);
        int gr = rowBase + r; int grc = gr < N ? gr : N-1;
        int bi = __ldg(bids + grc);
        const float* gp = g_gamma + (size_t)bi*256 + wn*64 + 2*t;
        const float* bp = g_beta  + (size_t)bi*256 + wn*64 + 2*t;
        #pragma unroll
        for (int nt=0; nt<8; nt++){
          float2 ga = *(const float2*)(gp + nt*8);
          float2 be = *(const float2*)(bp + nt*8);
          float v0 = fmaxf(fmaf((acc[mt][nt][2*h  ]-mu)*rs, ga.x, be.x), 0.f);
          float v1 = fmaxf(fmaf((acc[mt][nt][2*h+1]-mu)*rs, ga.y, be.y), 0.f);
          sts32(sb + OFF_A + (uint32_t)r*A_STR + (uint32_t)(wn*64+nt*8+2*t)*2,
                pack_h2(v0, v1));
        }
      }
    }
    __syncthreads();
  }

  // ================= GEMM2 =================
  zacc(acc);
  do_chunk(aBase, bB0, 0,   0, acc, g_w3h,       sb + OFF_W0, tid);
  do_chunk(aBase, bB1, 256, 0, acc, g_w3h + 128, sb + OFF_W1, tid);

  // ---- epilogue 2: relu(acc + b2) -> A ----
  {
    float2 bb[8];
    #pragma unroll
    for (int nt=0; nt<8; nt++) bb[nt] = *(const float2*)(b2 + wn*64 + nt*8 + 2*t);
    #pragma unroll
    for (int mt=0; mt<2; mt++){
      #pragma unroll
      for (int h=0; h<2; h++){
        int r = wm*32 + mt*16 + h*8 + g;
        #pragma unroll
        for (int nt=0; nt<8; nt++){
          float v0 = fmaxf(acc[mt][nt][2*h  ] + bb[nt].x, 0.f);
          float v1 = fmaxf(acc[mt][nt][2*h+1] + bb[nt].y, 0.f);
          sts32(sb + OFF_A + (uint32_t)r*A_STR + (uint32_t)(wn*64+nt*8+2*t)*2,
                pack_h2(v0, v1));
        }
      }
    }
    __syncthreads();
  }

  // ================= GEMM3 (cols 0..255) =================
  zacc(acc);
  do_chunk(aBase, bB0, 0,   0, acc, g_w3h + (size_t)256*256,       sb + OFF_W0, tid);
  do_chunk(aBase, bB1, 256, 0, acc, g_w3h + (size_t)256*256 + 128, sb + OFF_W1, tid);
  {
    float2 bb[8];
    #pragma unroll
    for (int nt=0; nt<8; nt++) bb[nt] = *(const float2*)(b3 + wn*64 + nt*8 + 2*t);
    #pragma unroll
    for (int mt=0; mt<2; mt++){
      #pragma unroll
      for (int h=0; h<2; h++){
        int r = wm*32 + mt*16 + h*8 + g;
        int gr = rowBase + r;
        if (gr < N){
          #pragma unroll
          for (int nt=0; nt<8; nt++){
            float2 o = make_float2(acc[mt][nt][2*h] + bb[nt].x,
                                   acc[mt][nt][2*h+1] + bb[nt].y);
            *(float2*)(out + (size_t)gr*512 + wn*64 + nt*8 + 2*t) = o;
          }
        }
      }
    }
  }

  // ================= GEMM3 (cols 256..511) =================
  zacc(acc);
  do_chunk(aBase, bB0, 0,   0, acc, nullptr, 0, tid);
  do_chunk(aBase, bB1, 256, 1, acc, nullptr, 0, tid);
  {
    float2 bb[8];
    #pragma unroll
    for (int nt=0; nt<8; nt++) bb[nt] = *(const float2*)(b3 + 256 + wn*64 + nt*8 + 2*t);
    #pragma unroll
    for (int mt=0; mt<2; mt++){
      #pragma unroll
      for (int h=0; h<2; h++){
        int r = wm*32 + mt*16 + h*8 + g;
        int gr = rowBase + r;
        if (gr < N){
          #pragma unroll
          for (int nt=0; nt<8; nt++){
            float2 o = make_float2(acc[mt][nt][2*h] + bb[nt].x,
                                   acc[mt][nt][2*h+1] + bb[nt].y);
            *(float2*)(out + (size_t)gr*512 + 256 + wn*64 + nt*8 + 2*t) = o;
          }
        }
      }
    }
  }
}

// ---------------- launch ----------------
extern "C" void kernel_launch(void* const* d_in, const int* in_sizes, int n_in,
                              void* d_out, int out_size){
  const float* x      = (const float*)d_in[0];
  const float* cond   = (const float*)d_in[1];
  const int*   bids   = (const int*)  d_in[2];
  const float* v_cond = (const float*)d_in[3];
  const float* g_cond = (const float*)d_in[4];
  const float* b_cond = (const float*)d_in[5];
  const float* v1     = (const float*)d_in[6];
  const float* g1     = (const float*)d_in[7];
  const float* v2     = (const float*)d_in[8];
  const float* g2     = (const float*)d_in[9];
  const float* b2     = (const float*)d_in[10];
  const float* v3     = (const float*)d_in[11];
  const float* g3     = (const float*)d_in[12];
  const float* b3     = (const float*)d_in[13];
  float* out = (float*)d_out;
  int N = in_sizes[0] / 256;

  wn_all<<<1536,256>>>(v1,g1, v2,g2, v3,g3, v_cond,g_cond);
  film_kernel<<<64,256>>>(cond, b_cond);

  cudaFuncSetAttribute(fused_kernel, cudaFuncAttributeMaxDynamicSharedMemorySize, SMEM_NEED);
  int blocks = (N + 127) / 128;
  fused_kernel<<<blocks, THREADS, SMEM_NEED>>>(x, bids, b2, b3, out, N);
}

// round 4
// speedup vs baseline: 1.8433x; 1.1131x over previous
#include <cuda_runtime.h>
#include <cuda_fp16.h>
#include <cstdint>
#include <cstddef>

#define THREADS 512
// ---- dynamic smem layout (bytes from base) ----
#define OFF_A    0            // A tile fp16 [128][264] -> 128*528 = 67584
#define A_STR    528
#define OFF_RED  67584        // 1024 floats = 4096
#define OFF_W0   71680        // weight buf fp16 [256][136] = 69632
#define OFF_W1   141312
#define WB_STR   272
#define WDELTA   (OFF_W1-OFF_W0)
#define SMEM_NEED 210944

// ---- precomputed weights (device globals) ----
__device__ __half g_w1h[256*256];
__device__ __half g_w2h[256*256];
__device__ __half g_w3h[512*256];
__device__ float  g_gamma[256*256];
__device__ float  g_beta [256*256];

// ---------------- helpers ----------------
__device__ __forceinline__ uint32_t smem_u32(const void* p){
  uint32_t a; asm("{ .reg .u64 t; cvta.to.shared.u64 t, %1; cvt.u32.u64 %0, t; }" : "=r"(a) : "l"(p));
  return a;
}
__device__ __forceinline__ float ldsf(uint32_t a){
  float v; asm volatile("ld.shared.f32 %0, [%1];" : "=f"(v) : "r"(a)); return v;
}
__device__ __forceinline__ void sts32(uint32_t a, uint32_t v){
  asm volatile("st.shared.b32 [%0], %1;" :: "r"(a), "r"(v));
}
__device__ __forceinline__ void stsf(uint32_t a, float v){
  asm volatile("st.shared.f32 [%0], %1;" :: "r"(a), "f"(v));
}
__device__ __forceinline__ void sts64(uint32_t a, uint32_t v0, uint32_t v1){
  asm volatile("st.shared.v2.b32 [%0], {%1,%2};" :: "r"(a), "r"(v0), "r"(v1));
}
__device__ __forceinline__ void cpasync16(uint32_t dst, const void* src){
  asm volatile("{ .reg .u64 gp; cvta.to.global.u64 gp, %1; cp.async.cg.shared.global [%0], [gp], 16; }"
               :: "r"(dst), "l"(src));
}
#define CPCOMMIT() asm volatile("cp.async.commit_group;" ::: "memory")
#define CPWAIT1()  asm volatile("cp.async.wait_group 1;" ::: "memory")
#define CPWAIT0()  asm volatile("cp.async.wait_group 0;" ::: "memory")

__device__ __forceinline__ void ldsm4(uint32_t* r, uint32_t a){
  asm volatile("ldmatrix.sync.aligned.m8n8.x4.shared.b16 {%0,%1,%2,%3}, [%4];"
    : "=r"(r[0]),"=r"(r[1]),"=r"(r[2]),"=r"(r[3]) : "r"(a));
}
__device__ __forceinline__ void mma16816(float* c, const uint32_t* a, uint32_t b0, uint32_t b1){
  asm volatile("mma.sync.aligned.m16n8k16.row.col.f32.f16.f16.f32 "
    "{%0,%1,%2,%3}, {%4,%5,%6,%7}, {%8,%9}, {%0,%1,%2,%3};"
    : "+f"(c[0]), "+f"(c[1]), "+f"(c[2]), "+f"(c[3])
    : "r"(a[0]),"r"(a[1]),"r"(a[2]),"r"(a[3]),"r"(b0),"r"(b1));
}
__device__ __forceinline__ uint32_t pack_h2(float x, float y){
  __half2 h = __floats2half2_rn(x, y);
  return *reinterpret_cast<uint32_t*>(&h);
}

// ---------------- merged precompute (ONE launch) ----------------
// blocks 0..255: w1 rows | 256..511: w2 | 512..1023: w3 | 1024..1535: film row j
__global__ void pre_all(const float* __restrict__ v1, const float* __restrict__ g1,
                        const float* __restrict__ v2, const float* __restrict__ g2,
                        const float* __restrict__ v3, const float* __restrict__ g3,
                        const float* __restrict__ vc, const float* __restrict__ gc,
                        const float* __restrict__ cond, const float* __restrict__ b_cond){
  int b = blockIdx.x, tid = threadIdx.x, lane = tid & 31, wid = tid >> 5;
  const float* v; const float* gs; __half* wh = nullptr; int row; int film = 0;
  if      (b < 256)  { v=v1; gs=g1; wh=g_w1h; row=b; }
  else if (b < 512)  { v=v2; gs=g2; wh=g_w2h; row=b-256; }
  else if (b < 1024) { v=v3; gs=g3; wh=g_w3h; row=b-512; }
  else               { v=vc; gs=gc; row=b-1024; film=1; }
  float val = v[(size_t)row*256 + tid];
  float sq = val*val;
  #pragma unroll
  for (int o=16;o;o>>=1) sq += __shfl_xor_sync(0xffffffffu, sq, o);
  __shared__ float red[8]; __shared__ float s_scale; __shared__ float wrow[256];
  if (lane==0) red[tid>>5] = sq;
  __syncthreads();
  if (tid==0){
    float tot=0.f;
    #pragma unroll
    for (int i=0;i<8;i++) tot += red[i];
    s_scale = gs[row]*rsqrtf(tot);
  }
  __syncthreads();
  float o = val * s_scale;
  if (!film){ wh[(size_t)row*256 + tid] = __float2half_rn(o); return; }

  // film: j = row; gamma/beta column j across all 256 groups
  wrow[tid] = o;
  __syncthreads();
  float w8[8];
  #pragma unroll
  for (int q=0;q<8;q++) w8[q] = wrow[lane + 32*q];
  float bc = b_cond[row];
  int j = row;
  #pragma unroll 1
  for (int gi=0; gi<32; gi++){
    int g = wid*32 + gi;
    const float* cp = cond + (size_t)g*256;
    float s = 0.f;
    #pragma unroll
    for (int q=0;q<8;q++) s = fmaf(w8[q], cp[lane + 32*q], s);
    #pragma unroll
    for (int o2=16;o2;o2>>=1) s += __shfl_xor_sync(0xffffffffu, s, o2);
    if (lane==0){
      float valr = s + bc;
      if (j < 256) g_gamma[(size_t)g*256 + j]         = valr + 1.f;
      else         g_beta [(size_t)g*256 + (j-256)]   = valr;
    }
  }
}

// ---------------- main kernel pieces ----------------
__device__ __forceinline__ void stage_async(const __half* __restrict__ base, uint32_t wbu, int tid){
  #pragma unroll
  for (int i=0;i<8;i++){
    int idx = tid + i*THREADS;
    int row = idx >> 4, c = idx & 15;
    cpasync16(wbu + (uint32_t)row*WB_STR + (uint32_t)c*16,
              base + (size_t)row*256 + c*8);
  }
}

__device__ __forceinline__ void mma_chunk(uint32_t aL0, uint32_t aL1,
    uint32_t bL0, uint32_t bL1, uint32_t bL2, uint32_t bL3, float acc[2][8][4]){
  #pragma unroll
  for (int k16=0; k16<8; k16++){
    uint32_t ko = (uint32_t)k16*32;
    uint32_t a0[4], a1[4], b0[4], b1[4], b2[4], b3[4];
    ldsm4(a0, aL0+ko); ldsm4(a1, aL1+ko);
    ldsm4(b0, bL0+ko); ldsm4(b1, bL1+ko); ldsm4(b2, bL2+ko); ldsm4(b3, bL3+ko);
    mma16816(acc[0][0], a0, b0[0], b0[1]);  mma16816(acc[1][0], a1, b0[0], b0[1]);
    mma16816(acc[0][1], a0, b0[2], b0[3]);  mma16816(acc[1][1], a1, b0[2], b0[3]);
    mma16816(acc[0][2], a0, b1[0], b1[1]);  mma16816(acc[1][2], a1, b1[0], b1[1]);
    mma16816(acc[0][3], a0, b1[2], b1[3]);  mma16816(acc[1][3], a1, b1[2], b1[3]);
    mma16816(acc[0][4], a0, b2[0], b2[1]);  mma16816(acc[1][4], a1, b2[0], b2[1]);
    mma16816(acc[0][5], a0, b2[2], b2[3]);  mma16816(acc[1][5], a1, b2[2], b2[3]);
    mma16816(acc[0][6], a0, b3[0], b3[1]);  mma16816(acc[1][6], a1, b3[0], b3[1]);
    mma16816(acc[0][7], a0, b3[2], b3[3]);  mma16816(acc[1][7], a1, b3[2], b3[3]);
  }
}

__device__ __forceinline__ void zacc(float acc[2][8][4]){
  #pragma unroll
  for (int i=0;i<2;i++)
    #pragma unroll
    for (int j=0;j<8;j++)
      #pragma unroll
      for (int q=0;q<4;q++) acc[i][j][q]=0.f;
}

__device__ __forceinline__ void do_chunk(const uint32_t* aL, const uint32_t* bL,
                                         uint32_t aOff, uint32_t wOff, int last,
                                         float acc[2][8][4],
                                         const __half* nextW, uint32_t nextBuf, int tid){
  if (last) CPWAIT0(); else CPWAIT1();
  __syncthreads();
  mma_chunk(aL[0]+aOff, aL[1]+aOff,
            bL[0]+wOff, bL[1]+wOff, bL[2]+wOff, bL[3]+wOff, acc);
  __syncthreads();
  if (nextW){ stage_async(nextW, nextBuf, tid); CPCOMMIT(); }
}

__global__ void __launch_bounds__(THREADS,1)
fused_kernel(const float* __restrict__ x, const int* __restrict__ bids,
             const float* __restrict__ b2, const float* __restrict__ b3,
             float* __restrict__ out, int N)
{
  extern __shared__ char smraw[];
  const uint32_t sb = smem_u32(smraw);

  const int tid = threadIdx.x, lane = tid & 31, wid = tid >> 5;
  const int wm = wid >> 2, wn = wid & 3;
  const int g = lane >> 2, t = lane & 3;
  const int rowBase = blockIdx.x * 128;

  // prefetch W1's two K-chunks
  stage_async(g_w1h,       sb + OFF_W0, tid); CPCOMMIT();
  stage_async(g_w1h + 128, sb + OFF_W1, tid); CPCOMMIT();

  // ---- load x tile -> A smem as fp16 ----
  #pragma unroll
  for (int i=0;i<16;i++){
    int idx = tid + i*THREADS;
    int r = idx >> 6, c4 = idx & 63;
    int gr = rowBase + r; int grc = gr < N ? gr : N-1;
    float4 v = *(const float4*)(x + (size_t)grc*256 + c4*4);
    sts64(sb + OFF_A + (uint32_t)r*A_STR + (uint32_t)c4*8,
          pack_h2(v.x, v.y), pack_h2(v.z, v.w));
  }

  // ldmatrix lane addressing
  const int mi = lane >> 3, r8 = lane & 7;
  uint32_t aL[2], bL[4];
  #pragma unroll
  for (int mt=0; mt<2; mt++)
    aL[mt] = sb + OFF_A + (uint32_t)((wm*32 + mt*16 + (mi&1)*8 + r8)*A_STR) + (uint32_t)((mi>>1)*16);
  #pragma unroll
  for (int n2=0; n2<4; n2++)
    bL[n2] = sb + OFF_W0 + (uint32_t)((wn*64 + n2*16 + (mi>>1)*8 + r8)*WB_STR) + (uint32_t)((mi&1)*16);

  const uint32_t redS = sb + OFF_RED;
  float acc[2][8][4];

  // ================= GEMM1 =================
  zacc(acc);
  do_chunk(aL, bL, 0,   0,      0, acc, g_w2h,       sb + OFF_W0, tid);
  do_chunk(aL, bL, 256, WDELTA, 0, acc, g_w2h + 128, sb + OFF_W1, tid);

  // ---- epilogue 1: layernorm + FiLM + relu -> A ----
  {
    #pragma unroll
    for (int mt=0; mt<2; mt++){
      #pragma unroll
      for (int h=0; h<2; h++){
        float S=0.f, Q=0.f;
        #pragma unroll
        for (int nt=0; nt<8; nt++){
          float u = acc[mt][nt][2*h], v = acc[mt][nt][2*h+1];
          S += u + v; Q = fmaf(u,u,Q); Q = fmaf(v,v,Q);
        }
        S += __shfl_xor_sync(0xffffffffu, S, 1); S += __shfl_xor_sync(0xffffffffu, S, 2);
        Q += __shfl_xor_sync(0xffffffffu, Q, 1); Q += __shfl_xor_sync(0xffffffffu, Q, 2);
        int r = wm*32 + mt*16 + h*8 + g;
        if (t==0){
          stsf(redS + (uint32_t)(r*4 + wn)*4,       S);
          stsf(redS + (uint32_t)(512 + r*4 + wn)*4, Q);
        }
      }
    }
    __syncthreads();
    #pragma unroll
    for (int mt=0; mt<2; mt++){
      #pragma unroll
      for (int h=0; h<2; h++){
        int r = wm*32 + mt*16 + h*8 + g;
        float S = ldsf(redS + (uint32_t)(r*4)*4)      + ldsf(redS + (uint32_t)(r*4+1)*4)
                + ldsf(redS + (uint32_t)(r*4+2)*4)    + ldsf(redS + (uint32_t)(r*4+3)*4);
        float Q = ldsf(redS + (uint32_t)(512+r*4)*4)  + ldsf(redS + (uint32_t)(512+r*4+1)*4)
                + ldsf(redS + (uint32_t)(512+r*4+2)*4)+ ldsf(redS + (uint32_t)(512+r*4+3)*4);
        float mu = S*(1.f/256.f);
        float var = fmaf(-mu, mu, Q*(1.f/256.f));
        float rs = rsqrtf(var + 1e-5f);
        int gr = rowBase + r; int grc = gr < N ? gr : N-1;
        int bi = __ldg(bids + grc);
        const float* gp = g_gamma + (size_t)bi*256 + wn*64 + 2*t;
        const float* bp = g_beta  + (size_t)bi*256 + wn*64 + 2*t;
        #pragma unroll
        for (int nt=0; nt<8; nt++){
          float2 ga = *(const float2*)(gp + nt*8);
          float2 be = *(const float2*)(bp + nt*8);
          float v0 = fmaxf(fmaf((acc[mt][nt][2*h  ]-mu)*rs, ga.x, be.x), 0.f);
          float v1 = fmaxf(fmaf((acc[mt][nt][2*h+1]-mu)*rs, ga.y, be.y), 0.f);
          sts32(sb + OFF_A + (uint32_t)r*A_STR + (uint32_t)(wn*64+nt*8+2*t)*2,
                pack_h2(v0, v1));
        }
      }
    }
    __syncthreads();
  }

  // ================= GEMM2 =================
  zacc(acc);
  do_chunk(aL, bL, 0,   0,      0, acc, g_w3h,       sb + OFF_W0, tid);
  do_chunk(aL, bL, 256, WDELTA, 0, acc, g_w3h + 128, sb + OFF_W1, tid);

  // ---- epilogue 2: relu(acc + b2) -> A ----
  {
    float2 bb[8];
    #pragma unroll
    for (int nt=0; nt<8; nt++) bb[nt] = *(const float2*)(b2 + wn*64 + nt*8 + 2*t);
    #pragma unroll
    for (int mt=0; mt<2; mt++){
      #pragma unroll
      for (int h=0; h<2; h++){
        int r = wm*32 + mt*16 + h*8 + g;
        #pragma unroll
        for (int nt=0; nt<8; nt++){
          float v0 = fmaxf(acc[mt][nt][2*h  ] + bb[nt].x, 0.f);
          float v1 = fmaxf(acc[mt][nt][2*h+1] + bb[nt].y, 0.f);
          sts32(sb + OFF_A + (uint32_t)r*A_STR + (uint32_t)(wn*64+nt*8+2*t)*2,
                pack_h2(v0, v1));
        }
      }
    }
    __syncthreads();
  }

  // ================= GEMM3 (cols 0..255) =================
  zacc(acc);
  do_chunk(aL, bL, 0,   0,      0, acc, g_w3h + (size_t)256*256,       sb + OFF_W0, tid);
  do_chunk(aL, bL, 256, WDELTA, 0, acc, g_w3h + (size_t)256*256 + 128, sb + OFF_W1, tid);
  {
    float2 bb[8];
    #pragma unroll
    for (int nt=0; nt<8; nt++) bb[nt] = *(const float2*)(b3 + wn*64 + nt*8 + 2*t);
    #pragma unroll
    for (int mt=0; mt<2; mt++){
      #pragma unroll
      for (int h=0; h<2; h++){
        int r = wm*32 + mt*16 + h*8 + g;
        int gr = rowBase + r;
        if (gr < N){
          #pragma unroll
          for (int nt=0; nt<8; nt++){
            float2 o = make_float2(acc[mt][nt][2*h] + bb[nt].x,
                                   acc[mt][nt][2*h+1] + bb[nt].y);
            *(float2*)(out + (size_t)gr*512 + wn*64 + nt*8 + 2*t) = o;
          }
        }
      }
    }
  }

  // ================= GEMM3 (cols 256..511) =================
  zacc(acc);
  do_chunk(aL, bL, 0,   0,      0, acc, nullptr, 0, tid);
  do_chunk(aL, bL, 256, WDELTA, 1, acc, nullptr, 0, tid);
  {
    float2 bb[8];
    #pragma unroll
    for (int nt=0; nt<8; nt++) bb[nt] = *(const float2*)(b3 + 256 + wn*64 + nt*8 + 2*t);
    #pragma unroll
    for (int mt=0; mt<2; mt++){
      #pragma unroll
      for (int h=0; h<2; h++){
        int r = wm*32 + mt*16 + h*8 + g;
        int gr = rowBase + r;
        if (gr < N){
          #pragma unroll
          for (int nt=0; nt<8; nt++){
            float2 o = make_float2(acc[mt][nt][2*h] + bb[nt].x,
                                   acc[mt][nt][2*h+1] + bb[nt].y);
            *(float2*)(out + (size_t)gr*512 + 256 + wn*64 + nt*8 + 2*t) = o;
          }
        }
      }
    }
  }
}

// ---------------- launch ----------------
extern "C" void kernel_launch(void* const* d_in, const int* in_sizes, int n_in,
                              void* d_out, int out_size){
  const float* x      = (const float*)d_in[0];
  const float* cond   = (const float*)d_in[1];
  const int*   bids   = (const int*)  d_in[2];
  const float* v_cond = (const float*)d_in[3];
  const float* g_cond = (const float*)d_in[4];
  const float* b_cond = (const float*)d_in[5];
  const float* v1     = (const float*)d_in[6];
  const float* g1     = (const float*)d_in[7];
  const float* v2     = (const float*)d_in[8];
  const float* g2     = (const float*)d_in[9];
  const float* b2     = (const float*)d_in[10];
  const float* v3     = (const float*)d_in[11];
  const float* g3     = (const float*)d_in[12];
  const float* b3     = (const float*)d_in[13];
  float* out = (float*)d_out;
  int N = in_sizes[0] / 256;

  pre_all<<<1536,256>>>(v1,g1, v2,g2, v3,g3, v_cond,g_cond, cond, b_cond);

  cudaFuncSetAttribute(fused_kernel, cudaFuncAttributeMaxDynamicSharedMemorySize, SMEM_NEED);
  int blocks = (N + 127) / 128;
  fused_kernel<<<blocks, THREADS, SMEM_NEED>>>(x, bids, b2, b3, out, N);
}

// round 5
// speedup vs baseline: 2.0875x; 1.1325x over previous
#include <cuda_runtime.h>
#include <cuda_fp16.h>
#include <cstdint>
#include <cstddef>

#define THREADS 256
#define BM      64
// ---- dynamic smem layout (bytes from base) ----
#define OFF_A    0            // A tile fp16 [64][264] -> 64*528 = 33792
#define A_STR    528
#define OFF_RED  33792        // 512 floats = 2048
#define OFF_W0   35840        // weight buf fp16 [256][72] = 36864
#define OFF_W1   72704
#define WB_STR   144
#define WDELTA   (OFF_W1-OFF_W0)
#define SMEM_NEED 109568

// ---- precomputed weights (device globals) ----
__device__ __half  g_w1h[256*256];
__device__ __half  g_w2h[256*256];
__device__ __half  g_w3h[512*256];
__device__ float2  g_film[256*256];   // (gamma, beta) interleaved

// ---------------- helpers ----------------
__device__ __forceinline__ uint32_t smem_u32(const void* p){
  uint32_t a; asm("{ .reg .u64 t; cvta.to.shared.u64 t, %1; cvt.u32.u64 %0, t; }" : "=r"(a) : "l"(p));
  return a;
}
__device__ __forceinline__ float ldsf(uint32_t a){
  float v; asm volatile("ld.shared.f32 %0, [%1];" : "=f"(v) : "r"(a)); return v;
}
__device__ __forceinline__ void sts32(uint32_t a, uint32_t v){
  asm volatile("st.shared.b32 [%0], %1;" :: "r"(a), "r"(v));
}
__device__ __forceinline__ void stsf(uint32_t a, float v){
  asm volatile("st.shared.f32 [%0], %1;" :: "r"(a), "f"(v));
}
__device__ __forceinline__ void sts64(uint32_t a, uint32_t v0, uint32_t v1){
  asm volatile("st.shared.v2.b32 [%0], {%1,%2};" :: "r"(a), "r"(v0), "r"(v1));
}
__device__ __forceinline__ void cpasync16(uint32_t dst, const void* src){
  asm volatile("{ .reg .u64 gp; cvta.to.global.u64 gp, %1; cp.async.cg.shared.global [%0], [gp], 16; }"
               :: "r"(dst), "l"(src));
}
#define CPCOMMIT() asm volatile("cp.async.commit_group;" ::: "memory")
#define CPWAIT1()  asm volatile("cp.async.wait_group 1;" ::: "memory")
#define CPWAIT0()  asm volatile("cp.async.wait_group 0;" ::: "memory")

__device__ __forceinline__ void ldsm4(uint32_t* r, uint32_t a){
  asm volatile("ldmatrix.sync.aligned.m8n8.x4.shared.b16 {%0,%1,%2,%3}, [%4];"
    : "=r"(r[0]),"=r"(r[1]),"=r"(r[2]),"=r"(r[3]) : "r"(a));
}
__device__ __forceinline__ void mma16816(float* c, const uint32_t* a, uint32_t b0, uint32_t b1){
  asm volatile("mma.sync.aligned.m16n8k16.row.col.f32.f16.f16.f32 "
    "{%0,%1,%2,%3}, {%4,%5,%6,%7}, {%8,%9}, {%0,%1,%2,%3};"
    : "+f"(c[0]), "+f"(c[1]), "+f"(c[2]), "+f"(c[3])
    : "r"(a[0]),"r"(a[1]),"r"(a[2]),"r"(a[3]),"r"(b0),"r"(b1));
}
__device__ __forceinline__ uint32_t pack_h2(float x, float y){
  __half2 h = __floats2half2_rn(x, y);
  return *reinterpret_cast<uint32_t*>(&h);
}

// ---------------- merged precompute (ONE launch) ----------------
__global__ void pre_all(const float* __restrict__ v1, const float* __restrict__ g1,
                        const float* __restrict__ v2, const float* __restrict__ g2,
                        const float* __restrict__ v3, const float* __restrict__ g3,
                        const float* __restrict__ vc, const float* __restrict__ gc,
                        const float* __restrict__ cond, const float* __restrict__ b_cond){
  int b = blockIdx.x, tid = threadIdx.x, lane = tid & 31, wid = tid >> 5;
  const float* v; const float* gs; __half* wh = nullptr; int row; int film = 0;
  if      (b < 256)  { v=v1; gs=g1; wh=g_w1h; row=b; }
  else if (b < 512)  { v=v2; gs=g2; wh=g_w2h; row=b-256; }
  else if (b < 1024) { v=v3; gs=g3; wh=g_w3h; row=b-512; }
  else               { v=vc; gs=gc; row=b-1024; film=1; }
  float val = v[(size_t)row*256 + tid];
  float sq = val*val;
  #pragma unroll
  for (int o=16;o;o>>=1) sq += __shfl_xor_sync(0xffffffffu, sq, o);
  __shared__ float red[8]; __shared__ float s_scale; __shared__ float wrow[256];
  if (lane==0) red[tid>>5] = sq;
  __syncthreads();
  if (tid==0){
    float tot=0.f;
    #pragma unroll
    for (int i=0;i<8;i++) tot += red[i];
    s_scale = gs[row]*rsqrtf(tot);
  }
  __syncthreads();
  float o = val * s_scale;
  if (!film){ wh[(size_t)row*256 + tid] = __float2half_rn(o); return; }

  // film: j = row of wc; j<256 -> gamma col j; j>=256 -> beta col j-256
  wrow[tid] = o;
  __syncthreads();
  float w8[8];
  #pragma unroll
  for (int q=0;q<8;q++) w8[q] = wrow[lane + 32*q];
  float bc = b_cond[row];
  int j = row;
  #pragma unroll 1
  for (int gi=0; gi<32; gi++){
    int g = wid*32 + gi;
    const float* cp = cond + (size_t)g*256;
    float s = 0.f;
    #pragma unroll
    for (int q=0;q<8;q++) s = fmaf(w8[q], cp[lane + 32*q], s);
    #pragma unroll
    for (int o2=16;o2;o2>>=1) s += __shfl_xor_sync(0xffffffffu, s, o2);
    if (lane==0){
      float valr = s + bc;
      if (j < 256) g_film[(size_t)g*256 + j].x       = valr + 1.f;
      else         g_film[(size_t)g*256 + (j-256)].y = valr;
    }
  }
}

// ---------------- main kernel pieces ----------------
// stage one [256 n x 64 k] fp16 chunk (32KB) into wbuf via cp.async
__device__ __forceinline__ void stage_async(const __half* __restrict__ base, uint32_t wbu, int tid){
  #pragma unroll
  for (int i=0;i<8;i++){
    int idx = tid + i*THREADS;          // 2048 x 16B
    int row = idx >> 3, c = idx & 7;    // 8 x 16B units per row (64 halves)
    cpasync16(wbu + (uint32_t)row*WB_STR + (uint32_t)c*16,
              base + (size_t)row*256 + c*8);
  }
}

__device__ __forceinline__ void mma_chunk(uint32_t aL0, uint32_t aL1,
    uint32_t bL0, uint32_t bL1, uint32_t bL2, uint32_t bL3, float acc[2][8][4]){
  #pragma unroll
  for (int k16=0; k16<4; k16++){
    uint32_t ko = (uint32_t)k16*32;
    uint32_t a0[4], a1[4], b0[4], b1[4], b2[4], b3[4];
    ldsm4(a0, aL0+ko); ldsm4(a1, aL1+ko);
    ldsm4(b0, bL0+ko); ldsm4(b1, bL1+ko); ldsm4(b2, bL2+ko); ldsm4(b3, bL3+ko);
    mma16816(acc[0][0], a0, b0[0], b0[1]);  mma16816(acc[1][0], a1, b0[0], b0[1]);
    mma16816(acc[0][1], a0, b0[2], b0[3]);  mma16816(acc[1][1], a1, b0[2], b0[3]);
    mma16816(acc[0][2], a0, b1[0], b1[1]);  mma16816(acc[1][2], a1, b1[0], b1[1]);
    mma16816(acc[0][3], a0, b1[2], b1[3]);  mma16816(acc[1][3], a1, b1[2], b1[3]);
    mma16816(acc[0][4], a0, b2[0], b2[1]);  mma16816(acc[1][4], a1, b2[0], b2[1]);
    mma16816(acc[0][5], a0, b2[2], b2[3]);  mma16816(acc[1][5], a1, b2[2], b2[3]);
    mma16816(acc[0][6], a0, b3[0], b3[1]);  mma16816(acc[1][6], a1, b3[0], b3[1]);
    mma16816(acc[0][7], a0, b3[2], b3[3]);  mma16816(acc[1][7], a1, b3[2], b3[3]);
  }
}

__device__ __forceinline__ void zacc(float acc[2][8][4]){
  #pragma unroll
  for (int i=0;i<2;i++)
    #pragma unroll
    for (int j=0;j<8;j++)
      #pragma unroll
      for (int q=0;q<4;q++) acc[i][j][q]=0.f;
}

// chunk i: wait its buffer, compute, prefetch chunk i+2 into the same buffer
__device__ __forceinline__ void do_chunk(const uint32_t* aL, const uint32_t* bL,
                                         int kc, int buf, int last,
                                         float acc[2][8][4],
                                         const __half* nextW, int tid){
  if (last) CPWAIT0(); else CPWAIT1();
  __syncthreads();
  uint32_t aOff = (uint32_t)kc*128;              // 64 halves per chunk
  uint32_t wOff = buf ? (uint32_t)WDELTA : 0u;
  mma_chunk(aL[0]+aOff, aL[1]+aOff,
            bL[0]+wOff, bL[1]+wOff, bL[2]+wOff, bL[3]+wOff, acc);
  __syncthreads();
  if (nextW){ stage_async(nextW, (buf ? bL[4]+WDELTA : bL[4]), tid); CPCOMMIT(); }
}

__global__ void __launch_bounds__(THREADS,2)
fused_kernel(const float* __restrict__ x, const int* __restrict__ bids,
             const float* __restrict__ b2, const float* __restrict__ b3,
             float* __restrict__ out, int N)
{
  extern __shared__ char smraw[];
  const uint32_t sb = smem_u32(smraw);

  const int tid = threadIdx.x, lane = tid & 31, wid = tid >> 5;
  const int wm = wid >> 2, wn = wid & 3;
  const int g = lane >> 2, t = lane & 3;
  const int rowBase = blockIdx.x * BM;

  // chunk sequence: pass p in {W1,W2,W3a,W3b}, kc in 0..3  (16 chunks)
  const __half* wbase[4] = { g_w1h, g_w2h, g_w3h, g_w3h + (size_t)256*256 };

  // prefetch chunks 0 and 1
  stage_async(wbase[0],      sb + OFF_W0, tid); CPCOMMIT();
  stage_async(wbase[0] + 64, sb + OFF_W1, tid); CPCOMMIT();

  // ---- load x tile -> A smem as fp16 ----
  #pragma unroll
  for (int i=0;i<16;i++){
    int idx = tid + i*THREADS;          // 4096 float4  (64 rows x 64 units)
    int r = idx >> 6, c4 = idx & 63;
    int gr = rowBase + r;
    float4 v = *(const float4*)(x + (size_t)gr*256 + c4*4);
    sts64(sb + OFF_A + (uint32_t)r*A_STR + (uint32_t)c4*8,
          pack_h2(v.x, v.y), pack_h2(v.z, v.w));
  }

  // ldmatrix lane addressing
  const int mi = lane >> 3, r8 = lane & 7;
  uint32_t aL[2], bL[5];
  #pragma unroll
  for (int mt=0; mt<2; mt++)
    aL[mt] = sb + OFF_A + (uint32_t)((wm*32 + mt*16 + (mi&1)*8 + r8)*A_STR) + (uint32_t)((mi>>1)*16);
  #pragma unroll
  for (int n2=0; n2<4; n2++)
    bL[n2] = sb + OFF_W0 + (uint32_t)((wn*64 + n2*16 + (mi>>1)*8 + r8)*WB_STR) + (uint32_t)((mi&1)*16);
  bL[4] = sb + OFF_W0;                  // staging base

  const uint32_t redS = sb + OFF_RED;
  float acc[2][8][4];

  // helper to get weight ptr for global chunk index (0..15), or null past end
  auto chunk_ptr = [&](int i)->const __half*{
    if (i >= 16) return nullptr;
    return wbase[i>>2] + (i&3)*64;
  };

  // ================= GEMM1 (chunks 0..3) =================
  zacc(acc);
  #pragma unroll
  for (int i=0;i<4;i++)
    do_chunk(aL, bL, i&3, i&1, 0, acc, chunk_ptr(i+2), tid);

  // ---- epilogue 1: layernorm + FiLM + relu -> A ----
  {
    #pragma unroll
    for (int mt=0; mt<2; mt++){
      #pragma unroll
      for (int h=0; h<2; h++){
        float S=0.f, Q=0.f;
        #pragma unroll
        for (int nt=0; nt<8; nt++){
          float u = acc[mt][nt][2*h], v = acc[mt][nt][2*h+1];
          S += u + v; Q = fmaf(u,u,Q); Q = fmaf(v,v,Q);
        }
        S += __shfl_xor_sync(0xffffffffu, S, 1); S += __shfl_xor_sync(0xffffffffu, S, 2);
        Q += __shfl_xor_sync(0xffffffffu, Q, 1); Q += __shfl_xor_sync(0xffffffffu, Q, 2);
        int r = wm*32 + mt*16 + h*8 + g;
        if (t==0){
          stsf(redS + (uint32_t)(r*4 + wn)*4,       S);
          stsf(redS + (uint32_t)(256 + r*4 + wn)*4, Q);
        }
      }
    }
    __syncthreads();
    #pragma unroll
    for (int mt=0; mt<2; mt++){
      #pragma unroll
      for (int h=0; h<2; h++){
        int r = wm*32 + mt*16 + h*8 + g;
        float S = ldsf(redS + (uint32_t)(r*4)*4)      + ldsf(redS + (uint32_t)(r*4+1)*4)
                + ldsf(redS + (uint32_t)(r*4+2)*4)    + ldsf(redS + (uint32_t)(r*4+3)*4);
        float Q = ldsf(redS + (uint32_t)(256+r*4)*4)  + ldsf(redS + (uint32_t)(256+r*4+1)*4)
                + ldsf(redS + (uint32_t)(256+r*4+2)*4)+ ldsf(redS + (uint32_t)(256+r*4+3)*4);
        float mu = S*(1.f/256.f);
        float var = fmaf(-mu, mu, Q*(1.f/256.f));
        float rs = rsqrtf(var + 1e-5f);
        int bi = __ldg(bids + rowBase + r);
        const float2* fp = g_film + (size_t)bi*256 + wn*64 + 2*t;
        #pragma unroll
        for (int nt=0; nt<8; nt++){
          float4 f0 = *(const float4*)(fp + nt*8);      // (g0,b0,g1,b1)
          float v0 = fmaxf(fmaf((acc[mt][nt][2*h  ]-mu)*rs, f0.x, f0.y), 0.f);
          float v1 = fmaxf(fmaf((acc[mt][nt][2*h+1]-mu)*rs, f0.z, f0.w), 0.f);
          sts32(sb + OFF_A + (uint32_t)r*A_STR + (uint32_t)(wn*64+nt*8+2*t)*2,
                pack_h2(v0, v1));
        }
      }
    }
    __syncthreads();
  }

  // ================= GEMM2 (chunks 4..7) =================
  zacc(acc);
  #pragma unroll
  for (int i=4;i<8;i++)
    do_chunk(aL, bL, i&3, i&1, 0, acc, chunk_ptr(i+2), tid);

  // ---- epilogue 2: relu(acc + b2) -> A ----
  {
    float2 bb[8];
    #pragma unroll
    for (int nt=0; nt<8; nt++) bb[nt] = *(const float2*)(b2 + wn*64 + nt*8 + 2*t);
    #pragma unroll
    for (int mt=0; mt<2; mt++){
      #pragma unroll
      for (int h=0; h<2; h++){
        int r = wm*32 + mt*16 + h*8 + g;
        #pragma unroll
        for (int nt=0; nt<8; nt++){
          float v0 = fmaxf(acc[mt][nt][2*h  ] + bb[nt].x, 0.f);
          float v1 = fmaxf(acc[mt][nt][2*h+1] + bb[nt].y, 0.f);
          sts32(sb + OFF_A + (uint32_t)r*A_STR + (uint32_t)(wn*64+nt*8+2*t)*2,
                pack_h2(v0, v1));
        }
      }
    }
    __syncthreads();
  }

  // ================= GEMM3 half A (chunks 8..11) =================
  zacc(acc);
  #pragma unroll
  for (int i=8;i<12;i++)
    do_chunk(aL, bL, i&3, i&1, 0, acc, chunk_ptr(i+2), tid);
  {
    float2 bb[8];
    #pragma unroll
    for (int nt=0; nt<8; nt++) bb[nt] = *(const float2*)(b3 + wn*64 + nt*8 + 2*t);
    #pragma unroll
    for (int mt=0; mt<2; mt++){
      #pragma unroll
      for (int h=0; h<2; h++){
        int gr = rowBase + wm*32 + mt*16 + h*8 + g;
        #pragma unroll
        for (int nt=0; nt<8; nt++){
          float2 o = make_float2(acc[mt][nt][2*h] + bb[nt].x,
                                 acc[mt][nt][2*h+1] + bb[nt].y);
          *(float2*)(out + (size_t)gr*512 + wn*64 + nt*8 + 2*t) = o;
        }
      }
    }
  }

  // ================= GEMM3 half B (chunks 12..15) =================
  zacc(acc);
  #pragma unroll
  for (int i=12;i<16;i++)
    do_chunk(aL, bL, i&3, i&1, (i==15), acc, chunk_ptr(i+2), tid);
  {
    float2 bb[8];
    #pragma unroll
    for (int nt=0; nt<8; nt++) bb[nt] = *(const float2*)(b3 + 256 + wn*64 + nt*8 + 2*t);
    #pragma unroll
    for (int mt=0; mt<2; mt++){
      #pragma unroll
      for (int h=0; h<2; h++){
        int gr = rowBase + wm*32 + mt*16 + h*8 + g;
        #pragma unroll
        for (int nt=0; nt<8; nt++){
          float2 o = make_float2(acc[mt][nt][2*h] + bb[nt].x,
                                 acc[mt][nt][2*h+1] + bb[nt].y);
          *(float2*)(out + (size_t)gr*512 + 256 + wn*64 + nt*8 + 2*t) = o;
        }
      }
    }
  }
}

// ---------------- launch ----------------
extern "C" void kernel_launch(void* const* d_in, const int* in_sizes, int n_in,
                              void* d_out, int out_size){
  const float* x      = (const float*)d_in[0];
  const float* cond   = (const float*)d_in[1];
  const int*   bids   = (const int*)  d_in[2];
  const float* v_cond = (const float*)d_in[3];
  const float* g_cond = (const float*)d_in[4];
  const float* b_cond = (const float*)d_in[5];
  const float* v1     = (const float*)d_in[6];
  const float* g1     = (const float*)d_in[7];
  const float* v2     = (const float*)d_in[8];
  const float* g2     = (const float*)d_in[9];
  const float* b2     = (const float*)d_in[10];
  const float* v3     = (const float*)d_in[11];
  const float* g3     = (const float*)d_in[12];
  const float* b3     = (const float*)d_in[13];
  float* out = (float*)d_out;
  int N = in_sizes[0] / 256;

  pre_all<<<1536,256>>>(v1,g1, v2,g2, v3,g3, v_cond,g_cond, cond, b_cond);

  cudaFuncSetAttribute(fused_kernel, cudaFuncAttributeMaxDynamicSharedMemorySize, SMEM_NEED);
  int blocks = (N + BM - 1) / BM;
  fused_kernel<<<blocks, THREADS, SMEM_NEED>>>(x, bids, b2, b3, out, N);
}